// round 15
// baseline (speedup 1.0000x reference)
#include <cuda_runtime.h>
#include <cuda_bf16.h>
#include <mma.h>
#include <math.h>
#include <stdint.h>

using namespace nvcuda;

#define B_  256
#define T_  512
#define I_  256
#define H_  512
#define G3  1536   // 3*H
#define NBLK 128

// ---------------- scratch (device globals: no allocation allowed) ----------
__device__ __align__(16) float g_igates[(size_t)T_ * B_ * G3]; // (t,b,g)
__device__ __align__(16) float g_h2[2][B_ * H_];               // double-buffered h
__device__ __align__(128) unsigned g_bars[8 * 32];             // 8 group ctrs
// bf16 splits (pre-split once per launch):
__device__ __align__(16) __nv_bfloat16 g_wsplit[2][16][96 * 512]; // w_hh per j-tile
__device__ __align__(16) __nv_bfloat16 g_xs[2][(size_t)B_ * T_ * I_]; // x
__device__ __align__(16) __nv_bfloat16 g_wihs[2][G3 * I_];     // w_ih

// ---------------- helpers ---------------------------------------------------
__device__ __forceinline__ unsigned pbf2(float a, float b) {
    __nv_bfloat162 t = __floats2bfloat162_rn(a, b);
    return *reinterpret_cast<unsigned*>(&t);
}
__device__ __forceinline__ float bhi(float x) {
    return __bfloat162float(__float2bfloat16(x));
}

// ======================= prep kernels: fp32 -> bf16 hi/lo ===================
__global__ __launch_bounds__(256) void prep_w_kernel(const float* __restrict__ w_hh) {
    int id = blockIdx.x * 256 + threadIdx.x;    // 98304, 8 k-elems each
    int jt = id / 6144;
    int rem = id % 6144;
    int r = rem >> 6;
    int kg = (rem & 63) * 8;
    int row = (r >> 5) * H_ + jt * 32 + (r & 31);

    float4 f0 = *(const float4*)&w_hh[(size_t)row * H_ + kg];
    float4 f1 = *(const float4*)&w_hh[(size_t)row * H_ + kg + 4];
    float x[8] = {f0.x, f0.y, f0.z, f0.w, f1.x, f1.y, f1.z, f1.w};
    uint4 hv, lv;
    unsigned* hp = (unsigned*)&hv;
    unsigned* lp = (unsigned*)&lv;
#pragma unroll
    for (int i = 0; i < 4; i++) {
        float a = x[2 * i], b = x[2 * i + 1];
        hp[i] = pbf2(bhi(a), bhi(b));
        lp[i] = pbf2(a - bhi(a), b - bhi(b));
    }
    *(uint4*)&g_wsplit[0][jt][r * 512 + kg] = hv;
    *(uint4*)&g_wsplit[1][jt][r * 512 + kg] = lv;
}

__global__ __launch_bounds__(256) void prep_x_kernel(const float* __restrict__ x) {
    size_t id = ((size_t)blockIdx.x * 256 + threadIdx.x) * 8;
    float4 f0 = *(const float4*)&x[id];
    float4 f1 = *(const float4*)&x[id + 4];
    float v[8] = {f0.x, f0.y, f0.z, f0.w, f1.x, f1.y, f1.z, f1.w};
    uint4 hv, lv;
    unsigned* hp = (unsigned*)&hv;
    unsigned* lp = (unsigned*)&lv;
#pragma unroll
    for (int i = 0; i < 4; i++) {
        float a = v[2 * i], b = v[2 * i + 1];
        hp[i] = pbf2(bhi(a), bhi(b));
        lp[i] = pbf2(a - bhi(a), b - bhi(b));
    }
    *(uint4*)&g_xs[0][id] = hv;
    *(uint4*)&g_xs[1][id] = lv;
}

__global__ __launch_bounds__(256) void prep_wih_kernel(const float* __restrict__ w_ih) {
    size_t id = ((size_t)blockIdx.x * 256 + threadIdx.x) * 8;
    float4 f0 = *(const float4*)&w_ih[id];
    float4 f1 = *(const float4*)&w_ih[id + 4];
    float v[8] = {f0.x, f0.y, f0.z, f0.w, f1.x, f1.y, f1.z, f1.w};
    uint4 hv, lv;
    unsigned* hp = (unsigned*)&hv;
    unsigned* lp = (unsigned*)&lv;
#pragma unroll
    for (int i = 0; i < 4; i++) {
        float a = v[2 * i], b = v[2 * i + 1];
        hp[i] = pbf2(bhi(a), bhi(b));
        lp[i] = pbf2(a - bhi(a), b - bhi(b));
    }
    *(uint4*)&g_wihs[0][id] = hv;
    *(uint4*)&g_wihs[1][id] = lv;
}

// ======================= Kernel 1: igates GEMM (wmma bf16-split) ============
// igates[t][b][g] = sum_i x[m][i] * w_ih[g][i] + bias[g],  m = b*T + t.
// Block: 128m x 128n, 8 warps (warp = 32m x 64n), K=256 in 4 chunks of 64.
#define TI_LD 72                     // bf16; 144B row, ldsm-friendly
#define TILE_E (128 * TI_LD)         // elems per tile
#define SMEM_I (4 * TILE_E * 2)      // xhi,xlo,whi,wlo = 73728 B
#define EP_LD 132                    // f32 epilogue stride

__global__ __launch_bounds__(256, 2) void igates_wmma_kernel(
        const float* __restrict__ bias) {
    extern __shared__ uint8_t smi[];
    __nv_bfloat16* tiles = (__nv_bfloat16*)smi;   // [4][128][TI_LD]
    float* ep = (float*)smi;

    const int tid = threadIdx.x;
    const int wid = tid >> 5;
    const int wm = wid & 3;          // m-group (32 rows)
    const int wn = wid >> 2;         // n-group (64 cols)
    const int n0 = blockIdx.x * 128;
    const int m0 = blockIdx.y * 128;

    wmma::fragment<wmma::accumulator, 16, 16, 16, float> acc[2][4];
#pragma unroll
    for (int mt = 0; mt < 2; mt++)
#pragma unroll
        for (int nt = 0; nt < 4; nt++) wmma::fill_fragment(acc[mt][nt], 0.0f);

    for (int kc = 0; kc < 4; kc++) {
        const int kb = kc * 64;
        __syncthreads();             // previous chunk's reads done
#pragma unroll
        for (int q = 0; q < 16; q++) {
            int id = tid + 256 * q;          // 4096 16B-pieces
            int which = id >> 10;            // 0 xhi, 1 xlo, 2 whi, 3 wlo
            int rem = id & 1023;
            int r = rem >> 3;
            int c8 = (rem & 7) * 8;
            const __nv_bfloat16* src =
                (which < 2) ? &g_xs[which][(size_t)(m0 + r) * I_ + kb + c8]
                            : &g_wihs[which - 2][(size_t)(n0 + r) * I_ + kb + c8];
            *(uint4*)&tiles[which * TILE_E + r * TI_LD + c8] = *(const uint4*)src;
        }
        __syncthreads();

        const __nv_bfloat16* xh = tiles;
        const __nv_bfloat16* xl = tiles + TILE_E;
        const __nv_bfloat16* wh = tiles + 2 * TILE_E;
        const __nv_bfloat16* wl = tiles + 3 * TILE_E;
#pragma unroll
        for (int ks = 0; ks < 4; ks++) {
            int kg = ks * 16;
            wmma::fragment<wmma::matrix_a, 16, 16, 16, __nv_bfloat16,
                           wmma::row_major> ahi[2], alo[2];
            wmma::fragment<wmma::matrix_b, 16, 16, 16, __nv_bfloat16,
                           wmma::col_major> bh[4], bl[4];
#pragma unroll
            for (int mt = 0; mt < 2; mt++) {
                wmma::load_matrix_sync(ahi[mt], &xh[(wm * 32 + mt * 16) * TI_LD + kg], TI_LD);
                wmma::load_matrix_sync(alo[mt], &xl[(wm * 32 + mt * 16) * TI_LD + kg], TI_LD);
            }
#pragma unroll
            for (int nt = 0; nt < 4; nt++) {
                wmma::load_matrix_sync(bh[nt], &wh[(wn * 64 + nt * 16) * TI_LD + kg], TI_LD);
                wmma::load_matrix_sync(bl[nt], &wl[(wn * 64 + nt * 16) * TI_LD + kg], TI_LD);
            }
#pragma unroll
            for (int mt = 0; mt < 2; mt++)
#pragma unroll
                for (int nt = 0; nt < 4; nt++) {
                    wmma::mma_sync(acc[mt][nt], ahi[mt], bh[nt], acc[mt][nt]);
                    wmma::mma_sync(acc[mt][nt], ahi[mt], bl[nt], acc[mt][nt]);
                    wmma::mma_sync(acc[mt][nt], alo[mt], bh[nt], acc[mt][nt]);
                }
        }
    }
    __syncthreads();                 // compute done before ep overwrite
#pragma unroll
    for (int mt = 0; mt < 2; mt++)
#pragma unroll
        for (int nt = 0; nt < 4; nt++)
            wmma::store_matrix_sync(&ep[(wm * 32 + mt * 16) * EP_LD + wn * 64 + nt * 16],
                                    acc[mt][nt], EP_LD, wmma::mem_row_major);
    __syncthreads();

    // write out: row m0+r -> (t,b); add bias; coalesced float4
    const int r = tid >> 1;
    const int ch = (tid & 1) * 64;
    const int t0 = m0 & (T_ - 1);
    const int bb = m0 >> 9;
    float* orow = &g_igates[((size_t)(t0 + r) * B_ + bb) * G3 + n0 + ch];
#pragma unroll
    for (int j = 0; j < 16; j++) {
        float4 v = *(float4*)&ep[r * EP_LD + ch + j * 4];
        float4 bi = __ldg((const float4*)&bias[n0 + ch + j * 4]);
        v.x += bi.x; v.y += bi.y; v.z += bi.z; v.w += bi.w;
        *(float4*)&orow[j * 4] = v;
    }
}

// ============== Kernel 2: persistent wmma GRU recurrence ====================
// 128 blocks x 512 thr, 1/SM. D[96, 32b] = W[96,512] @ H[32,512]^T per step.
// 12 MMA warps: kz = wid&3 (k-split 4 of 128), mg = wid>>2 (m 32 rows), n full.
// w_hi SMEM-stationary; w_lo streamed from L2 global; h full-K staged per step.
#define WS_LD 520                    // 1040B rows
#define HS_LD 520
#define WS_BYTES (96 * WS_LD * 2)    // 99,840
#define HS_OFF WS_BYTES
#define HS_SPLIT (32 * HS_LD * 2)    // 33,280 per split
#define SMEM_R (WS_BYTES + 2 * HS_SPLIT)   // 166,400
#define RED_LD 36

__global__ __launch_bounds__(512) void recur_kernel(const float* __restrict__ b_n) {
    extern __shared__ uint8_t sm[];
    __nv_bfloat16* wshi = (__nv_bfloat16*)sm;
    __nv_bfloat16* hshi = (__nv_bfloat16*)(sm + HS_OFF);
    __nv_bfloat16* hslo = (__nv_bfloat16*)(sm + HS_OFF + HS_SPLIT);
    float* redA = (float*)(sm + HS_OFF);              // reuse after k-loop
    float* redB = (float*)(sm + HS_OFF + 16384);

    const int tid = threadIdx.x;
    const int wid = tid >> 5;
    const int jt = blockIdx.x & 15;
    const int j0 = jt * 32;
    const int b0 = (blockIdx.x >> 4) * 32;
    const int grp = blockIdx.x >> 4;
    const int kz = wid & 3;                 // k-slice (wid<12)
    const int mg = wid >> 2;                // m-group 0..2

    // ---- stationary w_hi tile ----------------------------------------------
    {
        const __nv_bfloat16* ghi = g_wsplit[0][jt];
        for (int q = 0; q < 12; q++) {      // 6144 uint4
            int i = tid + 512 * q;
            int r = i >> 6, c = i & 63;
            *(uint4*)&wshi[r * WS_LD + c * 8] = *(const uint4*)&ghi[r * 512 + c * 8];
        }
    }
    const __nv_bfloat16* wlo_g = g_wsplit[1][jt];     // [96][512], L2-resident

    const int pj = tid & 31;
    const int pb = tid >> 5;                // batches pb, pb+16
    const float bnv = b_n[j0 + pj];
    const int sr = tid >> 4;                // staging row 0..31
    const int sc = tid & 15;                // staging k-group (32 k each)
    __syncthreads();

    for (int t = 0; t < T_; t++) {
        const float* __restrict__ hprev = g_h2[t & 1];
        float* __restrict__ hnext = g_h2[(t + 1) & 1];

        // ---- prefetch pointwise operands -----------------------------------
        float igv[2][3], hval[2];
#pragma unroll
        for (int half = 0; half < 2; half++) {
            int b = b0 + pb + 16 * half;
            size_t ib = ((size_t)t * B_ + b) * G3;
#pragma unroll
            for (int g = 0; g < 3; g++)
                igv[half][g] = __ldg(&g_igates[ib + g * H_ + j0 + pj]);
            hval[half] = __ldcg(&hprev[b * H_ + j0 + pj]);
        }

        // ---- stage FULL h (k=512) as bf16 hi/lo ----------------------------
        {
            const float* hp = &hprev[(size_t)(b0 + sr) * H_ + sc * 32];
            float4 f[8];
#pragma unroll
            for (int q = 0; q < 8; q++) f[q] = __ldcg((const float4*)(hp + q * 4));
            unsigned uh[16], ul[16];
#pragma unroll
            for (int q = 0; q < 8; q++) {
                uh[2 * q]     = pbf2(bhi(f[q].x), bhi(f[q].y));
                uh[2 * q + 1] = pbf2(bhi(f[q].z), bhi(f[q].w));
                ul[2 * q]     = pbf2(f[q].x - bhi(f[q].x), f[q].y - bhi(f[q].y));
                ul[2 * q + 1] = pbf2(f[q].z - bhi(f[q].z), f[q].w - bhi(f[q].w));
            }
            __nv_bfloat16* dh = &hshi[sr * HS_LD + sc * 32];
            __nv_bfloat16* dl = &hslo[sr * HS_LD + sc * 32];
#pragma unroll
            for (int w = 0; w < 4; w++) {
                *(uint4*)(dh + w * 8) = make_uint4(uh[4*w], uh[4*w+1], uh[4*w+2], uh[4*w+3]);
                *(uint4*)(dl + w * 8) = make_uint4(ul[4*w], ul[4*w+1], ul[4*w+2], ul[4*w+3]);
            }
        }
        __syncthreads();

        // ---- k-loop: no block syncs ----------------------------------------
        wmma::fragment<wmma::accumulator, 16, 16, 16, float> acc[2][2];
        if (wid < 12) {
#pragma unroll
            for (int mt = 0; mt < 2; mt++)
#pragma unroll
                for (int nt = 0; nt < 2; nt++) wmma::fill_fragment(acc[mt][nt], 0.0f);
            const int kb0 = kz * 128;
#pragma unroll
            for (int ks = 0; ks < 8; ks++) {
                int kg = kb0 + ks * 16;
                wmma::fragment<wmma::matrix_a, 16, 16, 16, __nv_bfloat16,
                               wmma::row_major> ahi[2], alo[2];
                wmma::fragment<wmma::matrix_b, 16, 16, 16, __nv_bfloat16,
                               wmma::col_major> bh[2], bl[2];
#pragma unroll
                for (int mt = 0; mt < 2; mt++) {
                    int rowb = mg * 32 + mt * 16;
                    wmma::load_matrix_sync(ahi[mt], &wshi[rowb * WS_LD + kg], WS_LD);
                    wmma::load_matrix_sync(alo[mt], &wlo_g[rowb * 512 + kg], 512);
                }
#pragma unroll
                for (int nt = 0; nt < 2; nt++) {
                    wmma::load_matrix_sync(bh[nt], &hshi[nt * 16 * HS_LD + kg], HS_LD);
                    wmma::load_matrix_sync(bl[nt], &hslo[nt * 16 * HS_LD + kg], HS_LD);
                }
#pragma unroll
                for (int mt = 0; mt < 2; mt++)
#pragma unroll
                    for (int nt = 0; nt < 2; nt++) {
                        wmma::mma_sync(acc[mt][nt], ahi[mt], bh[nt], acc[mt][nt]);
                        wmma::mma_sync(acc[mt][nt], ahi[mt], bl[nt], acc[mt][nt]);
                        wmma::mma_sync(acc[mt][nt], alo[mt], bh[nt], acc[mt][nt]);
                    }
            }
        }
        __syncthreads();    // hs reads done; red buffers may overwrite

        // ---- k-split reduction: 2 parallel rounds --------------------------
        if (wid < 12 && (kz == 0 || kz == 2)) {
            float* dst = (kz == 0) ? redA : redB;
#pragma unroll
            for (int mt = 0; mt < 2; mt++)
#pragma unroll
                for (int nt = 0; nt < 2; nt++)
                    wmma::store_matrix_sync(&dst[(mg * 32 + mt * 16) * RED_LD + nt * 16],
                                            acc[mt][nt], RED_LD, wmma::mem_row_major);
        }
        __syncthreads();
        if (wid < 12 && (kz == 1 || kz == 3)) {
            float* dst = (kz == 1) ? redA : redB;
#pragma unroll
            for (int mt = 0; mt < 2; mt++)
#pragma unroll
                for (int nt = 0; nt < 2; nt++) {
                    wmma::fragment<wmma::accumulator, 16, 16, 16, float> c;
                    float* p = &dst[(mg * 32 + mt * 16) * RED_LD + nt * 16];
                    wmma::load_matrix_sync(c, p, RED_LD, wmma::mem_row_major);
#pragma unroll
                    for (int e = 0; e < c.num_elements; e++)
                        c.x[e] += acc[mt][nt].x[e];
                    wmma::store_matrix_sync(p, c, RED_LD, wmma::mem_row_major);
                }
        }
        __syncthreads();

        // ---- GRU pointwise --------------------------------------------------
#pragma unroll
        for (int half = 0; half < 2; half++) {
            int bb = pb + 16 * half;
            float sr_ = redA[(0 * 32 + pj) * RED_LD + bb] + redB[(0 * 32 + pj) * RED_LD + bb];
            float sz_ = redA[(1 * 32 + pj) * RED_LD + bb] + redB[(1 * 32 + pj) * RED_LD + bb];
            float sn_ = redA[(2 * 32 + pj) * RED_LD + bb] + redB[(2 * 32 + pj) * RED_LD + bb];
            float r = 1.0f / (1.0f + expf(-(igv[half][0] + sr_)));
            float z = 1.0f / (1.0f + expf(-(igv[half][1] + sz_)));
            float n = tanhf(igv[half][2] + r * (sn_ + bnv));
            __stcg(&hnext[(b0 + bb) * H_ + j0 + pj], n + z * (hval[half] - n));
        }

        // ---- per-b-group barrier (16 blocks share these h rows) ------------
        __threadfence();
        __syncthreads();
        if (tid == 0) {
            atomicAdd(&g_bars[grp * 32], 1u);
            unsigned target = (unsigned)(t + 1) * 16u;
            volatile unsigned* p = &g_bars[grp * 32];
            while (*p < target) __nanosleep(32);
        }
        __syncthreads();
    }
}

// ======================= Kernel 3: final projection =========================
__global__ __launch_bounds__(128) void proj_kernel(
        const float* __restrict__ w_proj, const float* __restrict__ b_proj,
        float* __restrict__ out) {
    __shared__ float red[4];
    int b = blockIdx.x;
    float s = 0.f;
    for (int j = threadIdx.x; j < H_; j += 128)
        s += g_h2[0][b * H_ + j] * w_proj[j];   // T even -> final h in buf 0
#pragma unroll
    for (int o = 16; o; o >>= 1) s += __shfl_down_sync(0xffffffffu, s, o);
    if ((threadIdx.x & 31) == 0) red[threadIdx.x >> 5] = s;
    __syncthreads();
    if (threadIdx.x == 0)
        out[b] = red[0] + red[1] + red[2] + red[3] + b_proj[0];
}

__global__ void zero_kernel() {
    int i = blockIdx.x * 256 + threadIdx.x;
    if (i < B_ * H_) g_h2[0][i] = 0.f;
    if (i < 8 * 32) g_bars[i] = 0u;
}

// ======================= launch ============================================
extern "C" void kernel_launch(void* const* d_in, const int* in_sizes, int n_in,
                              void* d_out, int out_size) {
    const float* x      = (const float*)d_in[0];  // (B,T,I)
    const float* w_ih   = (const float*)d_in[1];  // (3H,I)
    const float* w_hh   = (const float*)d_in[2];  // (3H,H)
    const float* b      = (const float*)d_in[3];  // (3H)
    const float* b_n    = (const float*)d_in[4];  // (H)
    const float* w_proj = (const float*)d_in[5];  // (1,H)
    const float* b_proj = (const float*)d_in[6];  // (1)
    float* out = (float*)d_out;                   // (B)

    cudaFuncSetAttribute(recur_kernel,
                         cudaFuncAttributeMaxDynamicSharedMemorySize, SMEM_R);
    cudaFuncSetAttribute(igates_wmma_kernel,
                         cudaFuncAttributeMaxDynamicSharedMemorySize, SMEM_I);

    prep_x_kernel<<<16384, 256>>>(x);
    prep_wih_kernel<<<192, 256>>>(w_ih);
    prep_w_kernel<<<384, 256>>>(w_hh);
    igates_wmma_kernel<<<dim3(G3 / 128, (B_ * T_) / 128), 256, SMEM_I>>>(b);
    zero_kernel<<<(B_ * H_) / 256, 256>>>();
    recur_kernel<<<NBLK, 512, SMEM_R>>>(b_n);
    proj_kernel<<<B_, 128>>>(w_proj, b_proj, out);
}

// round 16
// speedup vs baseline: 1.8419x; 1.8419x over previous
#include <cuda_runtime.h>
#include <cuda_bf16.h>
#include <mma.h>
#include <math.h>
#include <stdint.h>

using namespace nvcuda;

#define B_  256
#define T_  512
#define I_  256
#define H_  512
#define G3  1536   // 3*H
#define NBLK 128

// ---------------- scratch (device globals: no allocation allowed) ----------
__device__ __align__(16) float g_igates[(size_t)T_ * B_ * G3]; // (t,b,g)
__device__ __align__(16) float g_h2[2][B_ * H_];               // double-buffered h
__device__ __align__(128) unsigned g_bars[8 * 32];             // 8 group ctrs
// bf16 splits (pre-split once per launch):
__device__ __align__(16) __nv_bfloat16 g_wsplit[2][16][96 * 512]; // w_hh per j-tile
__device__ __align__(16) __nv_bfloat16 g_xs[2][(size_t)B_ * T_ * I_]; // x
__device__ __align__(16) __nv_bfloat16 g_wihs[2][G3 * I_];     // w_ih

// ---------------- helpers ---------------------------------------------------
__device__ __forceinline__ unsigned pbf2(float a, float b) {
    __nv_bfloat162 t = __floats2bfloat162_rn(a, b);
    return *reinterpret_cast<unsigned*>(&t);
}
__device__ __forceinline__ float bhi(float x) {
    return __bfloat162float(__float2bfloat16(x));
}

// ======================= prep kernels: fp32 -> bf16 hi/lo ===================
__global__ __launch_bounds__(256) void prep_w_kernel(const float* __restrict__ w_hh) {
    int id = blockIdx.x * 256 + threadIdx.x;    // 98304, 8 k-elems each
    int jt = id / 6144;
    int rem = id % 6144;
    int r = rem >> 6;
    int kg = (rem & 63) * 8;
    int row = (r >> 5) * H_ + jt * 32 + (r & 31);

    float4 f0 = *(const float4*)&w_hh[(size_t)row * H_ + kg];
    float4 f1 = *(const float4*)&w_hh[(size_t)row * H_ + kg + 4];
    float x[8] = {f0.x, f0.y, f0.z, f0.w, f1.x, f1.y, f1.z, f1.w};
    uint4 hv, lv;
    unsigned* hp = (unsigned*)&hv;
    unsigned* lp = (unsigned*)&lv;
#pragma unroll
    for (int i = 0; i < 4; i++) {
        float a = x[2 * i], b = x[2 * i + 1];
        hp[i] = pbf2(bhi(a), bhi(b));
        lp[i] = pbf2(a - bhi(a), b - bhi(b));
    }
    *(uint4*)&g_wsplit[0][jt][r * 512 + kg] = hv;
    *(uint4*)&g_wsplit[1][jt][r * 512 + kg] = lv;
}

__global__ __launch_bounds__(256) void prep_x_kernel(const float* __restrict__ x) {
    size_t id = ((size_t)blockIdx.x * 256 + threadIdx.x) * 8;
    float4 f0 = *(const float4*)&x[id];
    float4 f1 = *(const float4*)&x[id + 4];
    float v[8] = {f0.x, f0.y, f0.z, f0.w, f1.x, f1.y, f1.z, f1.w};
    uint4 hv, lv;
    unsigned* hp = (unsigned*)&hv;
    unsigned* lp = (unsigned*)&lv;
#pragma unroll
    for (int i = 0; i < 4; i++) {
        float a = v[2 * i], b = v[2 * i + 1];
        hp[i] = pbf2(bhi(a), bhi(b));
        lp[i] = pbf2(a - bhi(a), b - bhi(b));
    }
    *(uint4*)&g_xs[0][id] = hv;
    *(uint4*)&g_xs[1][id] = lv;
}

__global__ __launch_bounds__(256) void prep_wih_kernel(const float* __restrict__ w_ih) {
    size_t id = ((size_t)blockIdx.x * 256 + threadIdx.x) * 8;
    float4 f0 = *(const float4*)&w_ih[id];
    float4 f1 = *(const float4*)&w_ih[id + 4];
    float v[8] = {f0.x, f0.y, f0.z, f0.w, f1.x, f1.y, f1.z, f1.w};
    uint4 hv, lv;
    unsigned* hp = (unsigned*)&hv;
    unsigned* lp = (unsigned*)&lv;
#pragma unroll
    for (int i = 0; i < 4; i++) {
        float a = v[2 * i], b = v[2 * i + 1];
        hp[i] = pbf2(bhi(a), bhi(b));
        lp[i] = pbf2(a - bhi(a), b - bhi(b));
    }
    *(uint4*)&g_wihs[0][id] = hv;
    *(uint4*)&g_wihs[1][id] = lv;
}

// ======================= Kernel 1: igates GEMM (wmma bf16-split) ============
// igates[t][b][g] = sum_i x[m][i] * w_ih[g][i] + bias[g],  m = b*T + t.
// Block: 128m x 128n, 8 warps (warp = 32m x 64n), K=256 in 4 chunks of 64.
#define TI_LD 72                     // bf16; 144B row, ldsm-friendly
#define TILE_E (128 * TI_LD)         // elems per tile
#define SMEM_I (4 * TILE_E * 2)      // xhi,xlo,whi,wlo = 73728 B
#define EP_LD 132                    // f32 epilogue stride

__global__ __launch_bounds__(256, 2) void igates_wmma_kernel(
        const float* __restrict__ bias) {
    extern __shared__ uint8_t smi[];
    __nv_bfloat16* tiles = (__nv_bfloat16*)smi;   // [4][128][TI_LD]
    float* ep = (float*)smi;

    const int tid = threadIdx.x;
    const int wid = tid >> 5;
    const int wm = wid & 3;          // m-group (32 rows)
    const int wn = wid >> 2;         // n-group (64 cols)
    const int n0 = blockIdx.x * 128;
    const int m0 = blockIdx.y * 128;

    wmma::fragment<wmma::accumulator, 16, 16, 16, float> acc[2][4];
#pragma unroll
    for (int mt = 0; mt < 2; mt++)
#pragma unroll
        for (int nt = 0; nt < 4; nt++) wmma::fill_fragment(acc[mt][nt], 0.0f);

    for (int kc = 0; kc < 4; kc++) {
        const int kb = kc * 64;
        __syncthreads();             // previous chunk's reads done
#pragma unroll
        for (int q = 0; q < 16; q++) {
            int id = tid + 256 * q;          // 4096 16B-pieces
            int which = id >> 10;            // 0 xhi, 1 xlo, 2 whi, 3 wlo
            int rem = id & 1023;
            int r = rem >> 3;
            int c8 = (rem & 7) * 8;
            const __nv_bfloat16* src =
                (which < 2) ? &g_xs[which][(size_t)(m0 + r) * I_ + kb + c8]
                            : &g_wihs[which - 2][(size_t)(n0 + r) * I_ + kb + c8];
            *(uint4*)&tiles[which * TILE_E + r * TI_LD + c8] = *(const uint4*)src;
        }
        __syncthreads();

        const __nv_bfloat16* xh = tiles;
        const __nv_bfloat16* xl = tiles + TILE_E;
        const __nv_bfloat16* wh = tiles + 2 * TILE_E;
        const __nv_bfloat16* wl = tiles + 3 * TILE_E;
#pragma unroll
        for (int ks = 0; ks < 4; ks++) {
            int kg = ks * 16;
            wmma::fragment<wmma::matrix_a, 16, 16, 16, __nv_bfloat16,
                           wmma::row_major> ahi[2], alo[2];
            wmma::fragment<wmma::matrix_b, 16, 16, 16, __nv_bfloat16,
                           wmma::col_major> bh[4], bl[4];
#pragma unroll
            for (int mt = 0; mt < 2; mt++) {
                wmma::load_matrix_sync(ahi[mt], &xh[(wm * 32 + mt * 16) * TI_LD + kg], TI_LD);
                wmma::load_matrix_sync(alo[mt], &xl[(wm * 32 + mt * 16) * TI_LD + kg], TI_LD);
            }
#pragma unroll
            for (int nt = 0; nt < 4; nt++) {
                wmma::load_matrix_sync(bh[nt], &wh[(wn * 64 + nt * 16) * TI_LD + kg], TI_LD);
                wmma::load_matrix_sync(bl[nt], &wl[(wn * 64 + nt * 16) * TI_LD + kg], TI_LD);
            }
#pragma unroll
            for (int mt = 0; mt < 2; mt++)
#pragma unroll
                for (int nt = 0; nt < 4; nt++) {
                    wmma::mma_sync(acc[mt][nt], ahi[mt], bh[nt], acc[mt][nt]);
                    wmma::mma_sync(acc[mt][nt], ahi[mt], bl[nt], acc[mt][nt]);
                    wmma::mma_sync(acc[mt][nt], alo[mt], bh[nt], acc[mt][nt]);
                }
        }
    }
    __syncthreads();                 // compute done before ep overwrite
#pragma unroll
    for (int mt = 0; mt < 2; mt++)
#pragma unroll
        for (int nt = 0; nt < 4; nt++)
            wmma::store_matrix_sync(&ep[(wm * 32 + mt * 16) * EP_LD + wn * 64 + nt * 16],
                                    acc[mt][nt], EP_LD, wmma::mem_row_major);
    __syncthreads();

    // write out: row m0+r -> (t,b); add bias; coalesced float4
    const int r = tid >> 1;
    const int ch = (tid & 1) * 64;
    const int t0 = m0 & (T_ - 1);
    const int bb = m0 >> 9;
    float* orow = &g_igates[((size_t)(t0 + r) * B_ + bb) * G3 + n0 + ch];
#pragma unroll
    for (int j = 0; j < 16; j++) {
        float4 v = *(float4*)&ep[r * EP_LD + ch + j * 4];
        float4 bi = __ldg((const float4*)&bias[n0 + ch + j * 4]);
        v.x += bi.x; v.y += bi.y; v.z += bi.z; v.w += bi.w;
        *(float4*)&orow[j * 4] = v;
    }
}

// ============== Kernel 2: persistent wmma GRU recurrence (R14, proven) ======
// 128 blocks x 512 thr, 1/SM. Per step per block:
//   D[96 = 3g x 32j, 32 b] = W[96,512] @ H[32,512]^T
// bf16 2-split (hh + hl + lh) in ONE f32 wmma accumulator.
// 12 warps each own an m16 x n16 D tile. BOTH w splits SMEM-stationary.
#define WS_LD 520                  // bf16; 1040B row
#define HS_LD 72                   // 144B row
#define RED_LD 36                  // f32; 144B row
#define WS_BYTES (96 * WS_LD * 2)  // 99,840 per split
#define HS_ELEMS (32 * HS_LD)      // 2304 per (buf, split)
#define SM_WHI 0
#define SM_WLO WS_BYTES
#define SM_HS  (2 * WS_BYTES)      // 199,680; 2 bufs x 2 splits x 4608B
#define SMEM_R (SM_HS + 4 * HS_ELEMS * 2)   // 218,112 B

__global__ __launch_bounds__(512) void recur_kernel(const float* __restrict__ b_n) {
    extern __shared__ uint8_t sm[];
    __nv_bfloat16* wshi = (__nv_bfloat16*)(sm + SM_WHI);
    __nv_bfloat16* wslo = (__nv_bfloat16*)(sm + SM_WLO);
    __nv_bfloat16* hsb  = (__nv_bfloat16*)(sm + SM_HS);  // [buf][split][32][HS_LD]
    float* red = (float*)(sm + SM_HS);                   // epilogue reuse

    const int tid = threadIdx.x;
    const int wid = tid >> 5;
    const int jt = blockIdx.x & 15;
    const int j0 = jt * 32;
    const int b0 = (blockIdx.x >> 4) * 32;
    const int grp = blockIdx.x >> 4;
    const int mt = wid >> 1;       // 0..5 (m-tile), valid for wid < 12
    const int nh = wid & 1;        // 0..1 (n-half)

    // ---- one-time copy of both w splits into SMEM --------------------------
    {
        const __nv_bfloat16* ghi = g_wsplit[0][jt];
        const __nv_bfloat16* glo = g_wsplit[1][jt];
        for (int q = 0; q < 12; q++) {          // 6144 uint4 per split
            int i = tid + 512 * q;
            int r = i >> 6, c = i & 63;
            *(uint4*)&wshi[r * WS_LD + c * 8] = *(const uint4*)&ghi[r * 512 + c * 8];
            *(uint4*)&wslo[r * WS_LD + c * 8] = *(const uint4*)&glo[r * 512 + c * 8];
        }
    }
    const int pj = tid & 31;
    const int pb = tid >> 5;                    // batches pb, pb+16
    const float bnv = b_n[j0 + pj];
    const int sr = tid >> 4;                    // staging row 0..31
    const int sc = tid & 15;                    // staging k-quad
    __syncthreads();

    for (int t = 0; t < T_; t++) {
        const float* __restrict__ hprev = g_h2[t & 1];
        float* __restrict__ hnext = g_h2[(t + 1) & 1];

        // ---- prefetch pointwise operands -----------------------------------
        float igv[2][3], hval[2];
#pragma unroll
        for (int half = 0; half < 2; half++) {
            int b = b0 + pb + 16 * half;
            size_t ib = ((size_t)t * B_ + b) * G3;
#pragma unroll
            for (int g = 0; g < 3; g++)
                igv[half][g] = __ldg(&g_igates[ib + g * H_ + j0 + pj]);
            hval[half] = __ldcg(&hprev[b * H_ + j0 + pj]);
        }

        // ---- stage h chunk 0 (hi/lo bf16) into buf 0 -----------------------
        {
            float4 v = __ldcg((const float4*)&hprev[(size_t)(b0 + sr) * H_ + sc * 4]);
            __nv_bfloat16* dhi = hsb;
            __nv_bfloat16* dlo = hsb + HS_ELEMS;
            *(unsigned*)&dhi[sr * HS_LD + sc * 4]     = pbf2(bhi(v.x), bhi(v.y));
            *(unsigned*)&dhi[sr * HS_LD + sc * 4 + 2] = pbf2(bhi(v.z), bhi(v.w));
            *(unsigned*)&dlo[sr * HS_LD + sc * 4]     = pbf2(v.x - bhi(v.x), v.y - bhi(v.y));
            *(unsigned*)&dlo[sr * HS_LD + sc * 4 + 2] = pbf2(v.z - bhi(v.z), v.w - bhi(v.w));
        }
        __syncthreads();

        wmma::fragment<wmma::accumulator, 16, 16, 16, float> acc;
        wmma::fill_fragment(acc, 0.0f);

        for (int cp = 0; cp < 8; cp++) {        // K = 8 chunks of 64
            float4 pf;
            if (cp < 7)
                pf = __ldcg((const float4*)
                        &hprev[(size_t)(b0 + sr) * H_ + (cp + 1) * 64 + sc * 4]);

            if (wid < 12) {
                const __nv_bfloat16* bhiP = hsb + (cp & 1) * 2 * HS_ELEMS;
                const __nv_bfloat16* bloP = bhiP + HS_ELEMS;
#pragma unroll
                for (int ks = 0; ks < 4; ks++) {
                    int kg = cp * 64 + ks * 16;
                    wmma::fragment<wmma::matrix_a, 16, 16, 16, __nv_bfloat16,
                                   wmma::row_major> ahi, alo;
                    wmma::fragment<wmma::matrix_b, 16, 16, 16, __nv_bfloat16,
                                   wmma::col_major> bhiF, bloF;
                    wmma::load_matrix_sync(ahi, &wshi[mt * 16 * WS_LD + kg], WS_LD);
                    wmma::load_matrix_sync(alo, &wslo[mt * 16 * WS_LD + kg], WS_LD);
                    wmma::load_matrix_sync(bhiF, &bhiP[nh * 16 * HS_LD + ks * 16], HS_LD);
                    wmma::load_matrix_sync(bloF, &bloP[nh * 16 * HS_LD + ks * 16], HS_LD);
                    wmma::mma_sync(acc, ahi, bhiF, acc);   // hi*hi
                    wmma::mma_sync(acc, ahi, bloF, acc);   // hi*lo
                    wmma::mma_sync(acc, alo, bhiF, acc);   // lo*hi
                }
            }
            if (cp < 7) {
                __nv_bfloat16* dhi = hsb + ((cp + 1) & 1) * 2 * HS_ELEMS;
                __nv_bfloat16* dlo = dhi + HS_ELEMS;
                *(unsigned*)&dhi[sr * HS_LD + sc * 4]     = pbf2(bhi(pf.x), bhi(pf.y));
                *(unsigned*)&dhi[sr * HS_LD + sc * 4 + 2] = pbf2(bhi(pf.z), bhi(pf.w));
                *(unsigned*)&dlo[sr * HS_LD + sc * 4]     = pbf2(pf.x - bhi(pf.x), pf.y - bhi(pf.y));
                *(unsigned*)&dlo[sr * HS_LD + sc * 4 + 2] = pbf2(pf.z - bhi(pf.z), pf.w - bhi(pf.w));
            }
            __syncthreads();
        }

        // ---- epilogue: acc -> SMEM (row = g*32+jj, col = batch) ------------
        if (wid < 12)
            wmma::store_matrix_sync(&red[(mt * 16) * RED_LD + nh * 16], acc,
                                    RED_LD, wmma::mem_row_major);
        __syncthreads();

        // ---- GRU pointwise --------------------------------------------------
#pragma unroll
        for (int half = 0; half < 2; half++) {
            int bb = pb + 16 * half;
            float sr_ = red[(0 * 32 + pj) * RED_LD + bb];
            float sz_ = red[(1 * 32 + pj) * RED_LD + bb];
            float sn_ = red[(2 * 32 + pj) * RED_LD + bb];
            float r = 1.0f / (1.0f + expf(-(igv[half][0] + sr_)));
            float z = 1.0f / (1.0f + expf(-(igv[half][1] + sz_)));
            float n = tanhf(igv[half][2] + r * (sn_ + bnv));
            __stcg(&hnext[(b0 + bb) * H_ + j0 + pj], n + z * (hval[half] - n));
        }

        // ---- per-b-group barrier (16 blocks share these h rows) ------------
        __threadfence();
        __syncthreads();
        if (tid == 0) {
            atomicAdd(&g_bars[grp * 32], 1u);
            unsigned target = (unsigned)(t + 1) * 16u;
            volatile unsigned* p = &g_bars[grp * 32];
            while (*p < target) __nanosleep(32);
        }
        __syncthreads();
    }
}

// ======================= Kernel 3: final projection =========================
__global__ __launch_bounds__(128) void proj_kernel(
        const float* __restrict__ w_proj, const float* __restrict__ b_proj,
        float* __restrict__ out) {
    __shared__ float red[4];
    int b = blockIdx.x;
    float s = 0.f;
    for (int j = threadIdx.x; j < H_; j += 128)
        s += g_h2[0][b * H_ + j] * w_proj[j];   // T even -> final h in buf 0
#pragma unroll
    for (int o = 16; o; o >>= 1) s += __shfl_down_sync(0xffffffffu, s, o);
    if ((threadIdx.x & 31) == 0) red[threadIdx.x >> 5] = s;
    __syncthreads();
    if (threadIdx.x == 0)
        out[b] = red[0] + red[1] + red[2] + red[3] + b_proj[0];
}

__global__ void zero_kernel() {
    int i = blockIdx.x * 256 + threadIdx.x;
    if (i < B_ * H_) g_h2[0][i] = 0.f;
    if (i < 8 * 32) g_bars[i] = 0u;
}

// ======================= launch ============================================
extern "C" void kernel_launch(void* const* d_in, const int* in_sizes, int n_in,
                              void* d_out, int out_size) {
    const float* x      = (const float*)d_in[0];  // (B,T,I)
    const float* w_ih   = (const float*)d_in[1];  // (3H,I)
    const float* w_hh   = (const float*)d_in[2];  // (3H,H)
    const float* b      = (const float*)d_in[3];  // (3H)
    const float* b_n    = (const float*)d_in[4];  // (H)
    const float* w_proj = (const float*)d_in[5];  // (1,H)
    const float* b_proj = (const float*)d_in[6];  // (1)
    float* out = (float*)d_out;                   // (B)

    cudaFuncSetAttribute(recur_kernel,
                         cudaFuncAttributeMaxDynamicSharedMemorySize, SMEM_R);
    cudaFuncSetAttribute(igates_wmma_kernel,
                         cudaFuncAttributeMaxDynamicSharedMemorySize, SMEM_I);

    prep_x_kernel<<<16384, 256>>>(x);
    prep_wih_kernel<<<192, 256>>>(w_ih);
    prep_w_kernel<<<384, 256>>>(w_hh);
    igates_wmma_kernel<<<dim3(G3 / 128, (B_ * T_) / 128), 256, SMEM_I>>>(b);
    zero_kernel<<<(B_ * H_) / 256, 256>>>();
    recur_kernel<<<NBLK, 512, SMEM_R>>>(b_n);
    proj_kernel<<<B_, 128>>>(w_proj, b_proj, out);
}

// round 17
// speedup vs baseline: 2.0328x; 1.1036x over previous
#include <cuda_runtime.h>
#include <cuda_bf16.h>
#include <mma.h>
#include <math.h>
#include <stdint.h>

using namespace nvcuda;

#define B_  256
#define T_  512
#define I_  256
#define H_  512
#define G3  1536   // 3*H
#define NBLK 128

// ---------------- scratch (device globals: no allocation allowed) ----------
__device__ __align__(16) float g_igates[(size_t)T_ * B_ * G3]; // (t,b,g)
__device__ __align__(16) float g_h2[2][B_ * H_];               // double-buffered h
__device__ __align__(128) unsigned g_bars[8 * 32];             // 8 group ctrs
// bf16 splits (pre-split once per launch):
__device__ __align__(16) __nv_bfloat16 g_wsplit[2][16][96 * 512]; // w_hh per j-tile
__device__ __align__(16) __nv_bfloat16 g_xs[2][(size_t)B_ * T_ * I_]; // x
__device__ __align__(16) __nv_bfloat16 g_wihs[2][G3 * I_];     // w_ih

// ---------------- helpers ---------------------------------------------------
__device__ __forceinline__ unsigned pbf2(float a, float b) {
    __nv_bfloat162 t = __floats2bfloat162_rn(a, b);
    return *reinterpret_cast<unsigned*>(&t);
}
__device__ __forceinline__ float bhi(float x) {
    return __bfloat162float(__float2bfloat16(x));
}

// ======================= prep kernels: fp32 -> bf16 hi/lo ===================
__global__ __launch_bounds__(256) void prep_w_kernel(const float* __restrict__ w_hh) {
    int id = blockIdx.x * 256 + threadIdx.x;    // 98304, 8 k-elems each
    int jt = id / 6144;
    int rem = id % 6144;
    int r = rem >> 6;
    int kg = (rem & 63) * 8;
    int row = (r >> 5) * H_ + jt * 32 + (r & 31);

    float4 f0 = *(const float4*)&w_hh[(size_t)row * H_ + kg];
    float4 f1 = *(const float4*)&w_hh[(size_t)row * H_ + kg + 4];
    float x[8] = {f0.x, f0.y, f0.z, f0.w, f1.x, f1.y, f1.z, f1.w};
    uint4 hv, lv;
    unsigned* hp = (unsigned*)&hv;
    unsigned* lp = (unsigned*)&lv;
#pragma unroll
    for (int i = 0; i < 4; i++) {
        float a = x[2 * i], b = x[2 * i + 1];
        hp[i] = pbf2(bhi(a), bhi(b));
        lp[i] = pbf2(a - bhi(a), b - bhi(b));
    }
    *(uint4*)&g_wsplit[0][jt][r * 512 + kg] = hv;
    *(uint4*)&g_wsplit[1][jt][r * 512 + kg] = lv;
}

__global__ __launch_bounds__(256) void prep_x_kernel(const float* __restrict__ x) {
    size_t id = ((size_t)blockIdx.x * 256 + threadIdx.x) * 8;
    float4 f0 = *(const float4*)&x[id];
    float4 f1 = *(const float4*)&x[id + 4];
    float v[8] = {f0.x, f0.y, f0.z, f0.w, f1.x, f1.y, f1.z, f1.w};
    uint4 hv, lv;
    unsigned* hp = (unsigned*)&hv;
    unsigned* lp = (unsigned*)&lv;
#pragma unroll
    for (int i = 0; i < 4; i++) {
        float a = v[2 * i], b = v[2 * i + 1];
        hp[i] = pbf2(bhi(a), bhi(b));
        lp[i] = pbf2(a - bhi(a), b - bhi(b));
    }
    *(uint4*)&g_xs[0][id] = hv;
    *(uint4*)&g_xs[1][id] = lv;
}

__global__ __launch_bounds__(256) void prep_wih_kernel(const float* __restrict__ w_ih) {
    size_t id = ((size_t)blockIdx.x * 256 + threadIdx.x) * 8;
    float4 f0 = *(const float4*)&w_ih[id];
    float4 f1 = *(const float4*)&w_ih[id + 4];
    float v[8] = {f0.x, f0.y, f0.z, f0.w, f1.x, f1.y, f1.z, f1.w};
    uint4 hv, lv;
    unsigned* hp = (unsigned*)&hv;
    unsigned* lp = (unsigned*)&lv;
#pragma unroll
    for (int i = 0; i < 4; i++) {
        float a = v[2 * i], b = v[2 * i + 1];
        hp[i] = pbf2(bhi(a), bhi(b));
        lp[i] = pbf2(a - bhi(a), b - bhi(b));
    }
    *(uint4*)&g_wihs[0][id] = hv;
    *(uint4*)&g_wihs[1][id] = lv;
}

// ======================= Kernel 1: igates GEMM (wmma bf16-split) ============
#define TI_LD 72                     // bf16; 144B row, ldsm-friendly
#define TILE_E (128 * TI_LD)
#define SMEM_I (4 * TILE_E * 2)      // 73728 B
#define EP_LD 132

__global__ __launch_bounds__(256, 2) void igates_wmma_kernel(
        const float* __restrict__ bias) {
    extern __shared__ uint8_t smi[];
    __nv_bfloat16* tiles = (__nv_bfloat16*)smi;   // [4][128][TI_LD]
    float* ep = (float*)smi;

    const int tid = threadIdx.x;
    const int wid = tid >> 5;
    const int wm = wid & 3;
    const int wn = wid >> 2;
    const int n0 = blockIdx.x * 128;
    const int m0 = blockIdx.y * 128;

    wmma::fragment<wmma::accumulator, 16, 16, 16, float> acc[2][4];
#pragma unroll
    for (int mt = 0; mt < 2; mt++)
#pragma unroll
        for (int nt = 0; nt < 4; nt++) wmma::fill_fragment(acc[mt][nt], 0.0f);

    for (int kc = 0; kc < 4; kc++) {
        const int kb = kc * 64;
        __syncthreads();
#pragma unroll
        for (int q = 0; q < 16; q++) {
            int id = tid + 256 * q;
            int which = id >> 10;
            int rem = id & 1023;
            int r = rem >> 3;
            int c8 = (rem & 7) * 8;
            const __nv_bfloat16* src =
                (which < 2) ? &g_xs[which][(size_t)(m0 + r) * I_ + kb + c8]
                            : &g_wihs[which - 2][(size_t)(n0 + r) * I_ + kb + c8];
            *(uint4*)&tiles[which * TILE_E + r * TI_LD + c8] = *(const uint4*)src;
        }
        __syncthreads();

        const __nv_bfloat16* xh = tiles;
        const __nv_bfloat16* xl = tiles + TILE_E;
        const __nv_bfloat16* wh = tiles + 2 * TILE_E;
        const __nv_bfloat16* wl = tiles + 3 * TILE_E;
#pragma unroll
        for (int ks = 0; ks < 4; ks++) {
            int kg = ks * 16;
            wmma::fragment<wmma::matrix_a, 16, 16, 16, __nv_bfloat16,
                           wmma::row_major> ahi[2], alo[2];
            wmma::fragment<wmma::matrix_b, 16, 16, 16, __nv_bfloat16,
                           wmma::col_major> bh[4], bl[4];
#pragma unroll
            for (int mt = 0; mt < 2; mt++) {
                wmma::load_matrix_sync(ahi[mt], &xh[(wm * 32 + mt * 16) * TI_LD + kg], TI_LD);
                wmma::load_matrix_sync(alo[mt], &xl[(wm * 32 + mt * 16) * TI_LD + kg], TI_LD);
            }
#pragma unroll
            for (int nt = 0; nt < 4; nt++) {
                wmma::load_matrix_sync(bh[nt], &wh[(wn * 64 + nt * 16) * TI_LD + kg], TI_LD);
                wmma::load_matrix_sync(bl[nt], &wl[(wn * 64 + nt * 16) * TI_LD + kg], TI_LD);
            }
#pragma unroll
            for (int mt = 0; mt < 2; mt++)
#pragma unroll
                for (int nt = 0; nt < 4; nt++) {
                    wmma::mma_sync(acc[mt][nt], ahi[mt], bh[nt], acc[mt][nt]);
                    wmma::mma_sync(acc[mt][nt], ahi[mt], bl[nt], acc[mt][nt]);
                    wmma::mma_sync(acc[mt][nt], alo[mt], bh[nt], acc[mt][nt]);
                }
        }
    }
    __syncthreads();
#pragma unroll
    for (int mt = 0; mt < 2; mt++)
#pragma unroll
        for (int nt = 0; nt < 4; nt++)
            wmma::store_matrix_sync(&ep[(wm * 32 + mt * 16) * EP_LD + wn * 64 + nt * 16],
                                    acc[mt][nt], EP_LD, wmma::mem_row_major);
    __syncthreads();

    const int r = tid >> 1;
    const int ch = (tid & 1) * 64;
    const int t0 = m0 & (T_ - 1);
    const int bb = m0 >> 9;
    float* orow = &g_igates[((size_t)(t0 + r) * B_ + bb) * G3 + n0 + ch];
#pragma unroll
    for (int j = 0; j < 16; j++) {
        float4 v = *(float4*)&ep[r * EP_LD + ch + j * 4];
        float4 bi = __ldg((const float4*)&bias[n0 + ch + j * 4]);
        v.x += bi.x; v.y += bi.y; v.z += bi.z; v.w += bi.w;
        *(float4*)&orow[j * 4] = v;
    }
}

// ============== Kernel 2: persistent wmma GRU recurrence ====================
// 128 blocks x 512 thr, 1/SM. D[96, 32b] = W[96,512] @ H[32,512]^T per step.
// BOTH w splits SMEM-stationary; h in 64-k double-buffered chunks (R14-proven).
// NEW tiling: 12 MMA warps = 3 m-groups (m32) x 4 k-quarters (ks=kz of each
// chunk); warp tile m32 x n32 -> 8 fragment loads per 12 MMAs (0.67 ratio,
// was 1.33) -> crossbar halved. 4-way k-split reduced in 2 parallel rounds.
#define WS_LD 520                  // bf16; 1040B row
#define HS_LD 72                   // 144B row
#define RED_LD 36                  // f32
#define WS_BYTES (96 * WS_LD * 2)  // 99,840 per split
#define HS_ELEMS (32 * HS_LD)      // 2304 per (buf, split)
#define SM_WHI 0
#define SM_WLO WS_BYTES
#define SM_HS  (2 * WS_BYTES)      // 199,680
#define RED_BYTES (96 * RED_LD * 4)       // 13,824
#define SMEM_R (SM_HS + 2 * RED_BYTES)    // 227,328 B (h region overlaid)

__global__ __launch_bounds__(512) void recur_kernel(const float* __restrict__ b_n) {
    extern __shared__ uint8_t sm[];
    __nv_bfloat16* wshi = (__nv_bfloat16*)(sm + SM_WHI);
    __nv_bfloat16* wslo = (__nv_bfloat16*)(sm + SM_WLO);
    __nv_bfloat16* hsb  = (__nv_bfloat16*)(sm + SM_HS);  // [buf][split][32][HS_LD]
    float* redA = (float*)(sm + SM_HS);                  // overlaid after k-loop
    float* redB = (float*)(sm + SM_HS + RED_BYTES);

    const int tid = threadIdx.x;
    const int wid = tid >> 5;
    const int jt = blockIdx.x & 15;
    const int j0 = jt * 32;
    const int b0 = (blockIdx.x >> 4) * 32;
    const int grp = blockIdx.x >> 4;
    const int kz = wid & 3;        // k-quarter within each chunk (wid < 12)
    const int mg = wid >> 2;       // m-group 0..2 (32 rows each)

    // ---- one-time copy of both w splits into SMEM --------------------------
    {
        const __nv_bfloat16* ghi = g_wsplit[0][jt];
        const __nv_bfloat16* glo = g_wsplit[1][jt];
        for (int q = 0; q < 12; q++) {
            int i = tid + 512 * q;
            int r = i >> 6, c = i & 63;
            *(uint4*)&wshi[r * WS_LD + c * 8] = *(const uint4*)&ghi[r * 512 + c * 8];
            *(uint4*)&wslo[r * WS_LD + c * 8] = *(const uint4*)&glo[r * 512 + c * 8];
        }
    }
    const int pj = tid & 31;
    const int pb = tid >> 5;                 // batches pb, pb+16
    const float bnv = b_n[j0 + pj];
    const int sr = tid >> 4;                 // staging row 0..31
    const int sc = tid & 15;                 // staging k-quad
    __syncthreads();

    for (int t = 0; t < T_; t++) {
        const float* __restrict__ hprev = g_h2[t & 1];
        float* __restrict__ hnext = g_h2[(t + 1) & 1];

        // ---- prefetch pointwise operands -----------------------------------
        float igv[2][3], hval[2];
#pragma unroll
        for (int half = 0; half < 2; half++) {
            int b = b0 + pb + 16 * half;
            size_t ib = ((size_t)t * B_ + b) * G3;
#pragma unroll
            for (int g = 0; g < 3; g++)
                igv[half][g] = __ldg(&g_igates[ib + g * H_ + j0 + pj]);
            hval[half] = __ldcg(&hprev[b * H_ + j0 + pj]);
        }

        // ---- stage h chunk 0 (hi/lo bf16) into buf 0 -----------------------
        {
            float4 v = __ldcg((const float4*)&hprev[(size_t)(b0 + sr) * H_ + sc * 4]);
            __nv_bfloat16* dhi = hsb;
            __nv_bfloat16* dlo = hsb + HS_ELEMS;
            *(unsigned*)&dhi[sr * HS_LD + sc * 4]     = pbf2(bhi(v.x), bhi(v.y));
            *(unsigned*)&dhi[sr * HS_LD + sc * 4 + 2] = pbf2(bhi(v.z), bhi(v.w));
            *(unsigned*)&dlo[sr * HS_LD + sc * 4]     = pbf2(v.x - bhi(v.x), v.y - bhi(v.y));
            *(unsigned*)&dlo[sr * HS_LD + sc * 4 + 2] = pbf2(v.z - bhi(v.z), v.w - bhi(v.w));
        }
        __syncthreads();

        wmma::fragment<wmma::accumulator, 16, 16, 16, float> acc[2][2];
#pragma unroll
        for (int mt = 0; mt < 2; mt++)
#pragma unroll
            for (int nt = 0; nt < 2; nt++) wmma::fill_fragment(acc[mt][nt], 0.0f);

        for (int cp = 0; cp < 8; cp++) {        // K = 8 chunks of 64
            float4 pf;
            if (cp < 7)
                pf = __ldcg((const float4*)
                        &hprev[(size_t)(b0 + sr) * H_ + (cp + 1) * 64 + sc * 4]);

            if (wid < 12) {
                const __nv_bfloat16* bhiP = hsb + (cp & 1) * 2 * HS_ELEMS;
                const __nv_bfloat16* bloP = bhiP + HS_ELEMS;
                const int kg = cp * 64 + kz * 16;    // this warp's k-quarter
                wmma::fragment<wmma::matrix_a, 16, 16, 16, __nv_bfloat16,
                               wmma::row_major> ahi[2], alo[2];
                wmma::fragment<wmma::matrix_b, 16, 16, 16, __nv_bfloat16,
                               wmma::col_major> bh[2], bl[2];
#pragma unroll
                for (int mt = 0; mt < 2; mt++) {
                    int rowb = mg * 32 + mt * 16;
                    wmma::load_matrix_sync(ahi[mt], &wshi[rowb * WS_LD + kg], WS_LD);
                    wmma::load_matrix_sync(alo[mt], &wslo[rowb * WS_LD + kg], WS_LD);
                }
#pragma unroll
                for (int nt = 0; nt < 2; nt++) {
                    wmma::load_matrix_sync(bh[nt], &bhiP[nt * 16 * HS_LD + kz * 16], HS_LD);
                    wmma::load_matrix_sync(bl[nt], &bloP[nt * 16 * HS_LD + kz * 16], HS_LD);
                }
#pragma unroll
                for (int mt = 0; mt < 2; mt++)
#pragma unroll
                    for (int nt = 0; nt < 2; nt++) {
                        wmma::mma_sync(acc[mt][nt], ahi[mt], bh[nt], acc[mt][nt]);
                        wmma::mma_sync(acc[mt][nt], ahi[mt], bl[nt], acc[mt][nt]);
                        wmma::mma_sync(acc[mt][nt], alo[mt], bh[nt], acc[mt][nt]);
                    }
            }
            if (cp < 7) {
                __nv_bfloat16* dhi = hsb + ((cp + 1) & 1) * 2 * HS_ELEMS;
                __nv_bfloat16* dlo = dhi + HS_ELEMS;
                *(unsigned*)&dhi[sr * HS_LD + sc * 4]     = pbf2(bhi(pf.x), bhi(pf.y));
                *(unsigned*)&dhi[sr * HS_LD + sc * 4 + 2] = pbf2(bhi(pf.z), bhi(pf.w));
                *(unsigned*)&dlo[sr * HS_LD + sc * 4]     = pbf2(pf.x - bhi(pf.x), pf.y - bhi(pf.y));
                *(unsigned*)&dlo[sr * HS_LD + sc * 4 + 2] = pbf2(pf.z - bhi(pf.z), pf.w - bhi(pf.w));
            }
            __syncthreads();
        }

        // ---- k-split reduction: 2 parallel rounds (kz0/2 store, kz1/3 add) -
        if (wid < 12 && (kz == 0 || kz == 2)) {
            float* dst = (kz == 0) ? redA : redB;
#pragma unroll
            for (int mt = 0; mt < 2; mt++)
#pragma unroll
                for (int nt = 0; nt < 2; nt++)
                    wmma::store_matrix_sync(&dst[(mg * 32 + mt * 16) * RED_LD + nt * 16],
                                            acc[mt][nt], RED_LD, wmma::mem_row_major);
        }
        __syncthreads();
        if (wid < 12 && (kz == 1 || kz == 3)) {
            float* dst = (kz == 1) ? redA : redB;
#pragma unroll
            for (int mt = 0; mt < 2; mt++)
#pragma unroll
                for (int nt = 0; nt < 2; nt++) {
                    wmma::fragment<wmma::accumulator, 16, 16, 16, float> c;
                    float* p = &dst[(mg * 32 + mt * 16) * RED_LD + nt * 16];
                    wmma::load_matrix_sync(c, p, RED_LD, wmma::mem_row_major);
#pragma unroll
                    for (int e = 0; e < c.num_elements; e++)
                        c.x[e] += acc[mt][nt].x[e];
                    wmma::store_matrix_sync(p, c, RED_LD, wmma::mem_row_major);
                }
        }
        __syncthreads();

        // ---- GRU pointwise --------------------------------------------------
#pragma unroll
        for (int half = 0; half < 2; half++) {
            int bb = pb + 16 * half;
            float sr_ = redA[(0 * 32 + pj) * RED_LD + bb] + redB[(0 * 32 + pj) * RED_LD + bb];
            float sz_ = redA[(1 * 32 + pj) * RED_LD + bb] + redB[(1 * 32 + pj) * RED_LD + bb];
            float sn_ = redA[(2 * 32 + pj) * RED_LD + bb] + redB[(2 * 32 + pj) * RED_LD + bb];
            float r = 1.0f / (1.0f + expf(-(igv[half][0] + sr_)));
            float z = 1.0f / (1.0f + expf(-(igv[half][1] + sz_)));
            float n = tanhf(igv[half][2] + r * (sn_ + bnv));
            __stcg(&hnext[(b0 + bb) * H_ + j0 + pj], n + z * (hval[half] - n));
        }

        // ---- per-b-group barrier (16 blocks share these h rows) ------------
        __threadfence();
        __syncthreads();
        if (tid == 0) {
            atomicAdd(&g_bars[grp * 32], 1u);
            unsigned target = (unsigned)(t + 1) * 16u;
            volatile unsigned* p = &g_bars[grp * 32];
            while (*p < target) __nanosleep(32);
        }
        __syncthreads();
    }
}

// ======================= Kernel 3: final projection =========================
__global__ __launch_bounds__(128) void proj_kernel(
        const float* __restrict__ w_proj, const float* __restrict__ b_proj,
        float* __restrict__ out) {
    __shared__ float red[4];
    int b = blockIdx.x;
    float s = 0.f;
    for (int j = threadIdx.x; j < H_; j += 128)
        s += g_h2[0][b * H_ + j] * w_proj[j];   // T even -> final h in buf 0
#pragma unroll
    for (int o = 16; o; o >>= 1) s += __shfl_down_sync(0xffffffffu, s, o);
    if ((threadIdx.x & 31) == 0) red[threadIdx.x >> 5] = s;
    __syncthreads();
    if (threadIdx.x == 0)
        out[b] = red[0] + red[1] + red[2] + red[3] + b_proj[0];
}

__global__ void zero_kernel() {
    int i = blockIdx.x * 256 + threadIdx.x;
    if (i < B_ * H_) g_h2[0][i] = 0.f;
    if (i < 8 * 32) g_bars[i] = 0u;
}

// ======================= launch ============================================
extern "C" void kernel_launch(void* const* d_in, const int* in_sizes, int n_in,
                              void* d_out, int out_size) {
    const float* x      = (const float*)d_in[0];  // (B,T,I)
    const float* w_ih   = (const float*)d_in[1];  // (3H,I)
    const float* w_hh   = (const float*)d_in[2];  // (3H,H)
    const float* b      = (const float*)d_in[3];  // (3H)
    const float* b_n    = (const float*)d_in[4];  // (H)
    const float* w_proj = (const float*)d_in[5];  // (1,H)
    const float* b_proj = (const float*)d_in[6];  // (1)
    float* out = (float*)d_out;                   // (B)

    cudaFuncSetAttribute(recur_kernel,
                         cudaFuncAttributeMaxDynamicSharedMemorySize, SMEM_R);
    cudaFuncSetAttribute(igates_wmma_kernel,
                         cudaFuncAttributeMaxDynamicSharedMemorySize, SMEM_I);

    prep_x_kernel<<<16384, 256>>>(x);
    prep_wih_kernel<<<192, 256>>>(w_ih);
    prep_w_kernel<<<384, 256>>>(w_hh);
    igates_wmma_kernel<<<dim3(G3 / 128, (B_ * T_) / 128), 256, SMEM_I>>>(b);
    zero_kernel<<<(B_ * H_) / 256, 256>>>();
    recur_kernel<<<NBLK, 512, SMEM_R>>>(b_n);
    proj_kernel<<<B_, 128>>>(w_proj, b_proj, out);
}